// round 10
// baseline (speedup 1.0000x reference)
#include <cuda_runtime.h>
#include <cuda_bf16.h>
#include <cstdint>

#define BATCH 2048
#define SEQ   128
#define FEAT  64
#define HID   512
#define NGATE 2048          // 4*HID, gate-interleaved: n = 4*j + g
#define TM    128
#define TN    128           // per warpgroup; CTA covers 2 N-tiles (n0, n0+1024)
#define TK    32
#define NTH   512
#define NCTA  128           // <=148 SMs, occ=1: spin-barrier liveness guaranteed

// smem: 3 stages x 6 segments of 10240B (128 rows x 80B; 64B data + 16B pad)
//   seg0 A_hi | seg1 A_mid | seg2 Ba_hi | seg3 Ba_mid | seg4 Bb_hi | seg5 Bb_mid
#define PB       80
#define SEGSZ    10240
#define STAGE    61440
#define NSTG     3
#define BIAS_OFF (NSTG * STAGE)           // 184320
#define SMEM_DYN (BIAS_OFF + 2048)        // 186368

// plane sizes (elements): [plane0 = hi | plane1 = mid]
#define POFF_U   (NGATE * HID)
#define POFF_W1  (NGATE * FEAT)
#define POFF_X   ((size_t)BATCH * SEQ * FEAT)
#define POFF_H   (BATCH * HID)

// ---------------- static device buffers (hi|mid planes combined) ----------------
__device__ __nv_bfloat16 g_U1[2 * NGATE * HID];
__device__ __nv_bfloat16 g_W1[2 * NGATE * FEAT];
__device__ __nv_bfloat16 g_U2[2 * NGATE * HID];
__device__ __nv_bfloat16 g_W2[2 * NGATE * HID];
__device__ __nv_bfloat16 g_x[2 * (size_t)BATCH * SEQ * FEAT];
__device__ __nv_bfloat16 g_h1[2][2 * BATCH * HID];   // [buf][plane*BATCH*HID]
__device__ __nv_bfloat16 g_h2[2][2 * BATCH * HID];
__device__ float g_c1[BATCH * HID], g_c2[BATCH * HID];
__device__ float g_b1i[NGATE], g_b2i[NGATE];
__device__ unsigned g_bar_count = 0;
__device__ unsigned g_bar_gen = 0;

// ---------------- PTX helpers ----------------
__device__ __forceinline__ uint32_t smem_u32(const void* p) {
    uint32_t a;
    asm("{ .reg .u64 t; cvta.to.shared.u64 t, %1; cvt.u32.u64 %0, t; }" : "=r"(a) : "l"(p));
    return a;
}
__device__ __forceinline__ void cpa(uint32_t dst, const void* src) {
    asm volatile("cp.async.cg.shared.global [%0], [%1], 16;" :: "r"(dst), "l"(src));
}
__device__ __forceinline__ void cp_commit() { asm volatile("cp.async.commit_group;"); }
template <int N> __device__ __forceinline__ void cp_wait() {
    asm volatile("cp.async.wait_group %0;" :: "n"(N));
}
__device__ __forceinline__ void ldm4(uint32_t* r, uint32_t addr) {
    asm volatile("ldmatrix.sync.aligned.m8n8.x4.shared.b16 {%0,%1,%2,%3}, [%4];"
        : "=r"(r[0]), "=r"(r[1]), "=r"(r[2]), "=r"(r[3]) : "r"(addr));
}
__device__ __forceinline__ void mma16816(float* c, const uint32_t* a, const uint32_t* b) {
    asm volatile("mma.sync.aligned.m16n8k16.row.col.f32.bf16.bf16.f32 "
        "{%0,%1,%2,%3}, {%4,%5,%6,%7}, {%8,%9}, {%0,%1,%2,%3};"
        : "+f"(c[0]), "+f"(c[1]), "+f"(c[2]), "+f"(c[3])
        : "r"(a[0]), "r"(a[1]), "r"(a[2]), "r"(a[3]), "r"(b[0]), "r"(b[1]));
}
__device__ __forceinline__ float sigmoid_(float v) { return 1.0f / (1.0f + __expf(-v)); }

// grid-wide sense-reversing barrier (128 CTAs, occ=1: residency guaranteed)
__device__ __forceinline__ void grid_barrier() {
    __syncthreads();
    if (threadIdx.x == 0) {
        unsigned my = *(volatile unsigned*)&g_bar_gen;
        __threadfence();
        unsigned prev = atomicAdd(&g_bar_count, 1u);
        if (prev == NCTA - 1) {
            atomicExch(&g_bar_count, 0u);
            __threadfence();
            atomicAdd(&g_bar_gen, 1u);
        } else {
            while (*(volatile unsigned*)&g_bar_gen == my) __nanosleep(40);
        }
        __threadfence();
    }
    __syncthreads();
}

// ---------------- one fused LSTM step: both N-tiles, shared A staging ----------------
__device__ __forceinline__ void tile_step(
    uint32_t sm_base, int m0, int n0a, int g, int wm, int wn, int lane, int tid,
    const __nv_bfloat16* __restrict__ Arec, uint32_t poffArec,              // [B,HID] hi plane
    const __nv_bfloat16* __restrict__ Urec, uint32_t poffU, int nRec,
    const __nv_bfloat16* __restrict__ Ain, int ldaIn, uint32_t poffAin,
    const __nv_bfloat16* __restrict__ Win, int ldbIn, uint32_t poffW, int nIn,
    const float* __restrict__ biasS, float* __restrict__ cst,
    __nv_bfloat16* __restrict__ hout, int first)
{
    __syncthreads();   // previous tile's readers must be done before restaging

    const int n0b = n0a + (NGATE / 2);

    // fixed per-thread staging role: one (r,c) slot in each of the 6 segments
    const int sr = (tid >> 2) & 127;
    const int sc = tid & 3;
    const uint32_t soff = (uint32_t)sr * PB + sc * 16;

    // running source pointers (elements; advance TK per K-iter)
    const __nv_bfloat16 *pA, *pBa, *pBb;
    uint32_t poA, poB;

    // per-warp ldmatrix addressing
    const int rA  = (lane & 7) + ((lane >> 3) & 1) * 8;
    const int kbA = (lane >> 4) * 8;
    const int rB  = (lane & 7) + ((lane >> 4) & 1) * 8;
    const int kbB = ((lane >> 3) & 1) * 8;
    const uint32_t aoff = (uint32_t)(wm * 64 + rA) * PB + kbA * 2;
    const uint32_t boff = (uint32_t)(2 + 2 * g) * SEGSZ + (uint32_t)(wn * 32 + rB) * PB + kbB * 2;

    float acc[4][4][4];
    #pragma unroll
    for (int a = 0; a < 4; ++a)
        #pragma unroll
        for (int b = 0; b < 4; ++b)
            #pragma unroll
            for (int c = 0; c < 4; ++c) acc[a][b][c] = 0.0f;

    const int nb = nRec + nIn;

    auto issue = [&](int itL, int s) {
        if (itL == 0 || itL == nRec) {
            if (itL < nRec) {
                pA  = Arec + (size_t)(m0 + sr) * HID + sc * 8;  poA = poffArec;
                pBa = Urec + (size_t)(n0a + sr) * HID + sc * 8;
                pBb = Urec + (size_t)(n0b + sr) * HID + sc * 8; poB = poffU;
            } else {
                pA  = Ain + (size_t)(m0 + sr) * ldaIn + sc * 8; poA = poffAin;
                pBa = Win + (size_t)(n0a + sr) * ldbIn + sc * 8;
                pBb = Win + (size_t)(n0b + sr) * ldbIn + sc * 8; poB = poffW;
            }
        }
        const uint32_t sb = sm_base + (uint32_t)s * STAGE + soff;
        cpa(sb + 0 * SEGSZ, pA);
        cpa(sb + 1 * SEGSZ, pA + poA);
        cpa(sb + 2 * SEGSZ, pBa);
        cpa(sb + 3 * SEGSZ, pBa + poB);
        cpa(sb + 4 * SEGSZ, pBb);
        cpa(sb + 5 * SEGSZ, pBb + poB);
        pA += TK; pBa += TK; pBb += TK;
    };

    // preload 2 stages
    issue(0, 0); cp_commit();
    if (1 < nb) issue(1, 1);
    cp_commit();

    int s_cmp = 0, s_nxt = 2;
    for (int it = 0; it < nb; ++it) {
        cp_wait<1>();
        __syncthreads();
        if (it + 2 < nb) issue(it + 2, s_nxt);
        cp_commit();
        if (++s_nxt == NSTG) s_nxt = 0;

        const uint32_t sb = sm_base + (uint32_t)s_cmp * STAGE;
        if (++s_cmp == NSTG) s_cmp = 0;

        #pragma unroll
        for (int ks = 0; ks < 2; ++ks) {
            uint32_t bh[2][4], bm[2][4];
            #pragma unroll
            for (int p = 0; p < 2; ++p) {
                uint32_t ba = sb + boff + (uint32_t)p * (16 * PB) + ks * 32;
                ldm4(bh[p], ba);
                ldm4(bm[p], ba + SEGSZ);
            }
            #pragma unroll
            for (int mp = 0; mp < 2; ++mp) {
                uint32_t ah[2][4], am[2][4];
                #pragma unroll
                for (int q = 0; q < 2; ++q) {
                    uint32_t aa = sb + aoff + (uint32_t)(mp * 2 + q) * (16 * PB) + ks * 32;
                    ldm4(ah[q], aa);
                    ldm4(am[q], aa + SEGSZ);
                }
                #pragma unroll
                for (int q = 0; q < 2; ++q)
                    #pragma unroll
                    for (int ni = 0; ni < 4; ++ni)
                        mma16816(acc[mp * 2 + q][ni], ah[q], &bh[ni >> 1][(ni & 1) * 2]);
                #pragma unroll
                for (int q = 0; q < 2; ++q)
                    #pragma unroll
                    for (int ni = 0; ni < 4; ++ni)
                        mma16816(acc[mp * 2 + q][ni], am[q], &bh[ni >> 1][(ni & 1) * 2]);
                #pragma unroll
                for (int q = 0; q < 2; ++q)
                    #pragma unroll
                    for (int ni = 0; ni < 4; ++ni)
                        mma16816(acc[mp * 2 + q][ni], ah[q], &bm[ni >> 1][(ni & 1) * 2]);
            }
        }
    }

    // ---------------- epilogue: bias + gate exchange + fused cell (packed I/O) ----------------
    const int jbase = ((n0a + g * (NGATE / 2)) >> 2) + wn * 8;
    const int mrow  = m0 + wm * 64 + (lane >> 2);
    #pragma unroll
    for (int mi = 0; mi < 4; ++mi) {
        #pragma unroll
        for (int ni = 0; ni < 4; ++ni) {
            const int nl = wn * 32 + ni * 8 + (lane & 3) * 2;
            const float bb0 = biasS[nl], bb1 = biasS[nl + 1];
            const int j0 = jbase + ni * 2;
            #pragma unroll
            for (int r = 0; r < 2; ++r) {
                const int m = mrow + mi * 16 + r * 8;
                const size_t idx = (size_t)m * HID + j0;
                float v0 = acc[mi][ni][r * 2 + 0] + bb0;
                float v1 = acc[mi][ni][r * 2 + 1] + bb1;
                float o0 = __shfl_xor_sync(0xffffffffu, v0, 1);
                float o1 = __shfl_xor_sync(0xffffffffu, v1, 1);
                // load c pair (float2) at quad leader, broadcast
                float cpx = 0.0f, cpy = 0.0f;
                if (!first) {
                    float2 cf = make_float2(0.0f, 0.0f);
                    if ((lane & 3) == 0) cf = *reinterpret_cast<const float2*>(cst + idx);
                    cpx = __shfl_sync(0xffffffffu, cf.x, lane & ~3);
                    cpy = __shfl_sync(0xffffffffu, cf.y, lane & ~3);
                }
                float cn = 0.0f, hv = 0.0f;
                if ((lane & 1) == 0) {
                    float cp = (lane & 2) ? cpy : cpx;
                    float iv = sigmoid_(v0), fv = sigmoid_(v1);
                    float ci = fmaxf(o0, 0.0f), ov = sigmoid_(o1);
                    cn = fv * cp + iv * ci;
                    hv = ov * fmaxf(cn, 0.0f);
                }
                // gather lane+2's results to quad leader, write wide
                float cn2 = __shfl_xor_sync(0xffffffffu, cn, 2);
                float hv2 = __shfl_xor_sync(0xffffffffu, hv, 2);
                if ((lane & 3) == 0) {
                    *reinterpret_cast<float2*>(cst + idx) = make_float2(cn, cn2);
                    __nv_bfloat16 h0 = __float2bfloat16(hv);
                    __nv_bfloat16 h1 = __float2bfloat16(hv2);
                    __nv_bfloat16 m0b = __float2bfloat16(hv - __bfloat162float(h0));
                    __nv_bfloat16 m1b = __float2bfloat16(hv2 - __bfloat162float(h1));
                    __nv_bfloat162 hp = __halves2bfloat162(h0, h1);
                    __nv_bfloat162 mp2 = __halves2bfloat162(m0b, m1b);
                    *reinterpret_cast<__nv_bfloat162*>(hout + idx) = hp;
                    *reinterpret_cast<__nv_bfloat162*>(hout + POFF_H + idx) = mp2;
                }
            }
        }
    }
}

// ---------------- persistent kernel ----------------
__global__ __launch_bounds__(NTH, 1) void lstm_persistent(
    const float* __restrict__ Wd, const float* __restrict__ bd, float* __restrict__ out)
{
    extern __shared__ char smem[];
    const uint32_t sm_base = smem_u32(smem);
    float* biasS = reinterpret_cast<float*>(smem + BIAS_OFF);   // [4][128]

    const int tid  = threadIdx.x;
    const int wid  = tid >> 5;
    const int lane = tid & 31;
    const int g    = wid >> 3;
    const int w8   = wid & 7;
    const int wm   = w8 >> 2;
    const int wn   = w8 & 3;
    const int bid  = blockIdx.x;
    const int m0   = (bid & 15) * TM;
    const int n0a  = (bid >> 4) * TN;

    if (tid < TN) {
        biasS[0 * TN + tid] = g_b1i[n0a + tid];
        biasS[1 * TN + tid] = g_b1i[n0a + (NGATE / 2) + tid];
        biasS[2 * TN + tid] = g_b2i[n0a + tid];
        biasS[3 * TN + tid] = g_b2i[n0a + (NGATE / 2) + tid];
    }
    __syncthreads();

    for (int p = 0; p <= SEQ; ++p) {
        if (p < SEQ) {
            const int t = p, cu = t & 1, pv = (t - 1) & 1;
            tile_step(sm_base, m0, n0a, g, wm, wn, lane, tid,
                      t ? g_h1[pv] : nullptr, (uint32_t)POFF_H,
                      g_U1, (uint32_t)POFF_U, t ? (HID / TK) : 0,
                      g_x + (size_t)t * FEAT, SEQ * FEAT, (uint32_t)POFF_X,
                      g_W1, FEAT, (uint32_t)POFF_W1, FEAT / TK,
                      biasS + g * TN, g_c1, g_h1[cu], t == 0);
        }
        if (p >= 1) {
            const int t = p - 1, cu = t & 1, pv = (t - 1) & 1;
            tile_step(sm_base, m0, n0a, g, wm, wn, lane, tid,
                      t ? g_h2[pv] : nullptr, (uint32_t)POFF_H,
                      g_U2, (uint32_t)POFF_U, t ? (HID / TK) : 0,
                      g_h1[cu], HID, (uint32_t)POFF_H,
                      g_W2, HID, (uint32_t)POFF_U, HID / TK,
                      biasS + (2 + g) * TN, g_c2, g_h2[cu], t == 0);
        }
        grid_barrier();
    }

    // dense head: 128 CTAs x 16 warps = 2048 batch rows
    {
        const int fin = (SEQ - 1) & 1;
        const int b = bid * 16 + wid;
        const __nv_bfloat16* rh = g_h2[fin] + (size_t)b * HID;
        const __nv_bfloat16* rm = rh + POFF_H;
        float s = 0.0f;
        #pragma unroll
        for (int k = lane; k < HID; k += 32)
            s += (__bfloat162float(rh[k]) + __bfloat162float(rm[k])) * Wd[k];
        #pragma unroll
        for (int o = 16; o > 0; o >>= 1) s += __shfl_xor_sync(0xffffffffu, s, o);
        if (lane == 0) out[b] = s + bd[0];
    }
}

// ---------------- prep kernels ----------------
__global__ void prep_weights_all(const float* __restrict__ U1, const float* __restrict__ W1,
                                 const float* __restrict__ U2, const float* __restrict__ W2)
{
    const int NU = NGATE * HID, NW = NGATE * FEAT;
    int idx = blockIdx.x * blockDim.x + threadIdx.x;
    const float* src; __nv_bfloat16* d; int K, li, po;
    if (idx < NU)               { src = U1; d = g_U1; K = HID;  li = idx;               po = NU; }
    else if (idx < NU + NW)     { src = W1; d = g_W1; K = FEAT; li = idx - NU;          po = NW; }
    else if (idx < 2 * NU + NW) { src = U2; d = g_U2; K = HID;  li = idx - NU - NW;     po = NU; }
    else if (idx < 3 * NU + NW) { src = W2; d = g_W2; K = HID;  li = idx - 2 * NU - NW; po = NU; }
    else return;
    int n = li / K, k = li - n * K;
    int col = (n & 3) * HID + (n >> 2);
    float v = src[(size_t)k * NGATE + col];
    __nv_bfloat16 h = __float2bfloat16(v);
    d[li] = h;
    d[po + li] = __float2bfloat16(v - __bfloat162float(h));
}

__global__ void prep_bias(const float* __restrict__ b1, const float* __restrict__ b2)
{
    int n = blockIdx.x * blockDim.x + threadIdx.x;
    if (n >= NGATE) return;
    int col = (n & 3) * HID + (n >> 2);
    g_b1i[n] = b1[col];
    g_b2i[n] = b2[col];
}

__global__ void prep_x(const float* __restrict__ x, int n)
{
    int i = blockIdx.x * blockDim.x + threadIdx.x;
    if (i >= n) return;
    float v = x[i];
    __nv_bfloat16 h = __float2bfloat16(v);
    g_x[i] = h;
    g_x[(size_t)n + i] = __float2bfloat16(v - __bfloat162float(h));
}

extern "C" void kernel_launch(void* const* d_in, const int* in_sizes, int n_in,
                              void* d_out, int out_size)
{
    const float* x  = (const float*)d_in[0];
    const float* W1 = (const float*)d_in[1];
    const float* U1 = (const float*)d_in[2];
    const float* b1 = (const float*)d_in[3];
    const float* W2 = (const float*)d_in[4];
    const float* U2 = (const float*)d_in[5];
    const float* b2 = (const float*)d_in[6];
    const float* Wd = (const float*)d_in[7];
    const float* bd = (const float*)d_in[8];
    float* out = (float*)d_out;

    cudaFuncSetAttribute(lstm_persistent, cudaFuncAttributeMaxDynamicSharedMemorySize, SMEM_DYN);

    {
        int ntot = 3 * NGATE * HID + NGATE * FEAT;
        prep_weights_all<<<(ntot + 255) / 256, 256>>>(U1, W1, U2, W2);
        prep_bias<<<(NGATE + 255) / 256, 256>>>(b1, b2);
        int nx = BATCH * SEQ * FEAT;
        prep_x<<<(nx + 255) / 256, 256>>>(x, nx);
    }

    lstm_persistent<<<NCTA, NTH, SMEM_DYN>>>(Wd, bd, out);
}

// round 12
// speedup vs baseline: 2.0227x; 2.0227x over previous
#include <cuda_runtime.h>
#include <cuda_fp16.h>
#include <cstdint>

#define BATCH 2048
#define SEQ   128
#define FEAT  64
#define HID   512
#define NGATE 2048          // 4*HID, gate-interleaved: n = 4*j + g
#define TM    128
#define TN    128           // per warpgroup; CTA covers 2 N-tiles (n0, n0+1024)
#define TK    32
#define NTH   512
#define NCTA  128           // <=148 SMs: distinct-SM placement, barrier liveness guaranteed

// smem: 2 stages x 3 segments of 10240B (128 rows x 80B; 64B data + 16B pad)
//   seg0 A | seg1 Ba | seg2 Bb
#define PB       80
#define SEGSZ    10240
#define STAGE    30720
#define NSTG     2
#define BIAS_OFF (NSTG * STAGE)           // 61440: four 128-float bias tiles
#define SMEM_DYN (BIAS_OFF + 2048)        // 63488

// ---------------- static device buffers (fp16) ----------------
__device__ __half g_U1[NGATE * HID];
__device__ __half g_W1[NGATE * FEAT];
__device__ __half g_U2[NGATE * HID];
__device__ __half g_W2[NGATE * HID];
__device__ __half g_x[(size_t)BATCH * SEQ * FEAT];
__device__ __half g_h1[2][BATCH * HID];
__device__ __half g_h2[2][BATCH * HID];
__device__ float g_c1[BATCH * HID], g_c2[BATCH * HID];
__device__ float g_b1i[NGATE], g_b2i[NGATE];
__device__ unsigned g_bar_count = 0;
__device__ unsigned g_bar_gen = 0;

// ---------------- PTX helpers ----------------
__device__ __forceinline__ uint32_t smem_u32(const void* p) {
    uint32_t a;
    asm("{ .reg .u64 t; cvta.to.shared.u64 t, %1; cvt.u32.u64 %0, t; }" : "=r"(a) : "l"(p));
    return a;
}
__device__ __forceinline__ void cpa(uint32_t dst, const void* src) {
    asm volatile("cp.async.cg.shared.global [%0], [%1], 16;" :: "r"(dst), "l"(src));
}
__device__ __forceinline__ void cp_commit() { asm volatile("cp.async.commit_group;"); }
template <int N> __device__ __forceinline__ void cp_wait() {
    asm volatile("cp.async.wait_group %0;" :: "n"(N));
}
__device__ __forceinline__ void ldm4(uint32_t* r, uint32_t addr) {
    asm volatile("ldmatrix.sync.aligned.m8n8.x4.shared.b16 {%0,%1,%2,%3}, [%4];"
        : "=r"(r[0]), "=r"(r[1]), "=r"(r[2]), "=r"(r[3]) : "r"(addr));
}
__device__ __forceinline__ void mma16816(float* c, const uint32_t* a, const uint32_t* b) {
    asm volatile("mma.sync.aligned.m16n8k16.row.col.f32.f16.f16.f32 "
        "{%0,%1,%2,%3}, {%4,%5,%6,%7}, {%8,%9}, {%0,%1,%2,%3};"
        : "+f"(c[0]), "+f"(c[1]), "+f"(c[2]), "+f"(c[3])
        : "r"(a[0]), "r"(a[1]), "r"(a[2]), "r"(a[3]), "r"(b[0]), "r"(b[1]));
}
__device__ __forceinline__ float sigmoid_(float v) { return 1.0f / (1.0f + __expf(-v)); }

// grid-wide sense-reversing barrier (128 CTAs on distinct SMs: liveness guaranteed)
__device__ __forceinline__ void grid_barrier() {
    __syncthreads();
    if (threadIdx.x == 0) {
        unsigned my = *(volatile unsigned*)&g_bar_gen;
        __threadfence();
        unsigned prev = atomicAdd(&g_bar_count, 1u);
        if (prev == NCTA - 1) {
            atomicExch(&g_bar_count, 0u);
            __threadfence();
            atomicAdd(&g_bar_gen, 1u);
        } else {
            while (*(volatile unsigned*)&g_bar_gen == my) __nanosleep(40);
        }
        __threadfence();
    }
    __syncthreads();
}

// ---------------- one fused LSTM step: both N-tiles, shared A staging, fp16 single-term ----------------
__device__ __forceinline__ void tile_step(
    uint32_t sm_base, int m0, int n0a, int g, int wm, int wn, int lane, int tid,
    const __half* __restrict__ Arec,
    const __half* __restrict__ Urec, int nRec,
    const __half* __restrict__ Ain, int ldaIn,
    const __half* __restrict__ Win, int ldbIn, int nIn,
    const float* __restrict__ biasS, float* __restrict__ cst,
    __half* __restrict__ hout, int first)
{
    __syncthreads();   // previous tile's readers must be done before restaging

    const int n0b = n0a + (NGATE / 2);

    // fixed per-thread staging role: one (r,c) 16B slot in each of the 3 segments
    const int sr = (tid >> 2) & 127;
    const int sc = tid & 3;
    const uint32_t soff = (uint32_t)sr * PB + sc * 16;

    const __half *pA, *pBa, *pBb;

    // per-warp ldmatrix addressing
    const int rA  = (lane & 7) + ((lane >> 3) & 1) * 8;
    const int kbA = (lane >> 4) * 8;
    const int rB  = (lane & 7) + ((lane >> 4) & 1) * 8;
    const int kbB = ((lane >> 3) & 1) * 8;
    const uint32_t aoff = (uint32_t)(wm * 64 + rA) * PB + kbA * 2;                  // seg0
    const uint32_t boff = (uint32_t)(1 + g) * SEGSZ + (uint32_t)(wn * 32 + rB) * PB + kbB * 2;

    float acc[4][4][4];
    #pragma unroll
    for (int a = 0; a < 4; ++a)
        #pragma unroll
        for (int b = 0; b < 4; ++b)
            #pragma unroll
            for (int c = 0; c < 4; ++c) acc[a][b][c] = 0.0f;

    const int nb = nRec + nIn;

    auto issue = [&](int itL, int s) {
        if (itL == 0 || itL == nRec) {
            if (itL < nRec) {
                pA  = Arec + (size_t)(m0 + sr) * HID + sc * 8;
                pBa = Urec + (size_t)(n0a + sr) * HID + sc * 8;
                pBb = Urec + (size_t)(n0b + sr) * HID + sc * 8;
            } else {
                pA  = Ain + (size_t)(m0 + sr) * ldaIn + sc * 8;
                pBa = Win + (size_t)(n0a + sr) * ldbIn + sc * 8;
                pBb = Win + (size_t)(n0b + sr) * ldbIn + sc * 8;
            }
        }
        const uint32_t sb = sm_base + (uint32_t)s * STAGE + soff;
        cpa(sb + 0 * SEGSZ, pA);
        cpa(sb + 1 * SEGSZ, pBa);
        cpa(sb + 2 * SEGSZ, pBb);
        pA += TK; pBa += TK; pBb += TK;
    };

    issue(0, 0);
    cp_commit();

    for (int it = 0; it < nb; ++it) {
        if (it + 1 < nb) {
            issue(it + 1, (it + 1) & 1);
            cp_commit();
            cp_wait<1>();
        } else {
            cp_wait<0>();
        }
        __syncthreads();

        const uint32_t sb = sm_base + (uint32_t)(it & 1) * STAGE;
        #pragma unroll
        for (int ks = 0; ks < 2; ++ks) {
            uint32_t bv[2][4];
            #pragma unroll
            for (int p = 0; p < 2; ++p)
                ldm4(bv[p], sb + boff + (uint32_t)p * (16 * PB) + ks * 32);
            uint32_t av[4][4];
            #pragma unroll
            for (int mi = 0; mi < 4; ++mi)
                ldm4(av[mi], sb + aoff + (uint32_t)mi * (16 * PB) + ks * 32);
            #pragma unroll
            for (int mi = 0; mi < 4; ++mi)
                #pragma unroll
                for (int ni = 0; ni < 4; ++ni)
                    mma16816(acc[mi][ni], av[mi], &bv[ni >> 1][(ni & 1) * 2]);
        }
        __syncthreads();
    }

    // epilogue: bias + gate exchange + fused cell
    const int jbase = ((n0a + g * (NGATE / 2)) >> 2) + wn * 8;
    #pragma unroll
    for (int mi = 0; mi < 4; ++mi) {
        #pragma unroll
        for (int ni = 0; ni < 4; ++ni) {
            const int nl = wn * 32 + ni * 8 + (lane & 3) * 2;
            const float bb0 = biasS[nl], bb1 = biasS[nl + 1];
            #pragma unroll
            for (int r = 0; r < 2; ++r) {
                float v0 = acc[mi][ni][r * 2 + 0] + bb0;
                float v1 = acc[mi][ni][r * 2 + 1] + bb1;
                float o0 = __shfl_xor_sync(0xffffffffu, v0, 1);
                float o1 = __shfl_xor_sync(0xffffffffu, v1, 1);
                if ((lane & 1) == 0) {
                    const int m = m0 + wm * 64 + mi * 16 + (lane >> 2) + r * 8;
                    const int j = jbase + ni * 2 + ((lane & 3) >> 1);
                    const size_t idx = (size_t)m * HID + j;
                    float cp = first ? 0.0f : cst[idx];
                    float iv = sigmoid_(v0), fv = sigmoid_(v1);
                    float ci = fmaxf(o0, 0.0f), ov = sigmoid_(o1);
                    float cn = fv * cp + iv * ci;
                    cst[idx] = cn;
                    float hv = ov * fmaxf(cn, 0.0f);
                    hout[idx] = __float2half(hv);
                }
            }
        }
    }
}

// ---------------- persistent kernel: all 128 steps, both layers, dense head ----------------
__global__ __launch_bounds__(NTH, 1) void lstm_persistent(
    const float* __restrict__ Wd, const float* __restrict__ bd, float* __restrict__ out)
{
    extern __shared__ char smem[];
    const uint32_t sm_base = smem_u32(smem);
    float* biasS = reinterpret_cast<float*>(smem + BIAS_OFF);   // [4][128]: L1a,L1b,L2a,L2b

    const int tid  = threadIdx.x;
    const int wid  = tid >> 5;
    const int lane = tid & 31;
    const int g    = wid >> 3;          // warpgroup 0/1 -> N-tile a/b
    const int w8   = wid & 7;
    const int wm   = w8 >> 2;
    const int wn   = w8 & 3;
    const int bid  = blockIdx.x;
    const int m0   = (bid & 15) * TM;
    const int n0a  = (bid >> 4) * TN;

    if (tid < TN) {
        biasS[0 * TN + tid] = g_b1i[n0a + tid];
        biasS[1 * TN + tid] = g_b1i[n0a + (NGATE / 2) + tid];
        biasS[2 * TN + tid] = g_b2i[n0a + tid];
        biasS[3 * TN + tid] = g_b2i[n0a + (NGATE / 2) + tid];
    }
    __syncthreads();

    // phase p: L1(t=p) and L2(t=p-1); both depend only on pre-barrier data
    for (int p = 0; p <= SEQ; ++p) {
        if (p < SEQ) {
            const int t = p, cu = t & 1, pv = (t - 1) & 1;
            tile_step(sm_base, m0, n0a, g, wm, wn, lane, tid,
                      t ? g_h1[pv] : nullptr,
                      g_U1, t ? (HID / TK) : 0,
                      g_x + (size_t)t * FEAT, SEQ * FEAT,
                      g_W1, FEAT, FEAT / TK,
                      biasS + g * TN, g_c1, g_h1[cu], t == 0);
        }
        if (p >= 1) {
            const int t = p - 1, cu = t & 1, pv = (t - 1) & 1;
            tile_step(sm_base, m0, n0a, g, wm, wn, lane, tid,
                      t ? g_h2[pv] : nullptr,
                      g_U2, t ? (HID / TK) : 0,
                      g_h1[cu], HID,
                      g_W2, HID, HID / TK,
                      biasS + (2 + g) * TN, g_c2, g_h2[cu], t == 0);
        }
        grid_barrier();
    }

    // dense head: 128 CTAs x 16 warps = 2048 batch rows
    {
        const int fin = (SEQ - 1) & 1;
        const int b = bid * 16 + wid;
        const __half* rh = g_h2[fin] + (size_t)b * HID;
        float s = 0.0f;
        #pragma unroll
        for (int k = lane; k < HID; k += 32)
            s += __half2float(rh[k]) * Wd[k];
        #pragma unroll
        for (int o = 16; o > 0; o >>= 1) s += __shfl_xor_sync(0xffffffffu, s, o);
        if (lane == 0) out[b] = s + bd[0];
    }
}

// ---------------- prep kernels ----------------
__global__ void prep_weights_all(const float* __restrict__ U1, const float* __restrict__ W1,
                                 const float* __restrict__ U2, const float* __restrict__ W2)
{
    const int NU = NGATE * HID, NW = NGATE * FEAT;
    int idx = blockIdx.x * blockDim.x + threadIdx.x;
    const float* src; __half* d; int K, li;
    if (idx < NU)               { src = U1; d = g_U1; K = HID;  li = idx; }
    else if (idx < NU + NW)     { src = W1; d = g_W1; K = FEAT; li = idx - NU; }
    else if (idx < 2 * NU + NW) { src = U2; d = g_U2; K = HID;  li = idx - NU - NW; }
    else if (idx < 3 * NU + NW) { src = W2; d = g_W2; K = HID;  li = idx - 2 * NU - NW; }
    else return;
    int n = li / K, k = li - n * K;
    int col = (n & 3) * HID + (n >> 2);          // gate-interleave: n = 4j+g
    d[li] = __float2half(src[(size_t)k * NGATE + col]);
}

__global__ void prep_bias(const float* __restrict__ b1, const float* __restrict__ b2)
{
    int n = blockIdx.x * blockDim.x + threadIdx.x;
    if (n >= NGATE) return;
    int col = (n & 3) * HID + (n >> 2);
    g_b1i[n] = b1[col];
    g_b2i[n] = b2[col];
}

__global__ void prep_x(const float* __restrict__ x, int n)
{
    int i = blockIdx.x * blockDim.x + threadIdx.x;
    if (i >= n) return;
    g_x[i] = __float2half(x[i]);
}

extern "C" void kernel_launch(void* const* d_in, const int* in_sizes, int n_in,
                              void* d_out, int out_size)
{
    const float* x  = (const float*)d_in[0];
    const float* W1 = (const float*)d_in[1];
    const float* U1 = (const float*)d_in[2];
    const float* b1 = (const float*)d_in[3];
    const float* W2 = (const float*)d_in[4];
    const float* U2 = (const float*)d_in[5];
    const float* b2 = (const float*)d_in[6];
    const float* Wd = (const float*)d_in[7];
    const float* bd = (const float*)d_in[8];
    float* out = (float*)d_out;

    cudaFuncSetAttribute(lstm_persistent, cudaFuncAttributeMaxDynamicSharedMemorySize, SMEM_DYN);

    {
        int ntot = 3 * NGATE * HID + NGATE * FEAT;
        prep_weights_all<<<(ntot + 255) / 256, 256>>>(U1, W1, U2, W2);
        prep_bias<<<(NGATE + 255) / 256, 256>>>(b1, b2);
        int nx = BATCH * SEQ * FEAT;
        prep_x<<<(nx + 255) / 256, 256>>>(x, nx);
    }

    lstm_persistent<<<NCTA, NTH, SMEM_DYN>>>(Wd, bd, out);
}

// round 14
// speedup vs baseline: 2.2701x; 1.1223x over previous
#include <cuda_runtime.h>
#include <cuda_fp16.h>
#include <cstdint>

#define BATCH 2048
#define SEQ   128
#define FEAT  64
#define HID   512
#define NGATE 2048          // 4*HID, gate-interleaved: n = 4*j + g
#define TM    128
#define TN    128           // per warpgroup; CTA covers 2 N-tiles (n0, n0+1024)
#define TK    64
#define NTH   512
#define NCTA  128           // <=148 SMs: distinct-SM placement, barrier liveness guaranteed

// smem: 2 stages x 3 segments of 18432B (128 rows x 144B; 128B data + 16B pad)
//   seg0 A | seg1 Ba | seg2 Bb
#define PB       144
#define SEGSZ    18432
#define STAGE    55296
#define NSTG     2
#define BIAS_OFF (NSTG * STAGE)           // 110592: four 128-float bias tiles
#define SMEM_DYN (BIAS_OFF + 2048)        // 112640

// ---------------- static device buffers (fp16) ----------------
__device__ __half g_U1[NGATE * HID];
__device__ __half g_W1[NGATE * FEAT];
__device__ __half g_U2[NGATE * HID];
__device__ __half g_W2[NGATE * HID];
__device__ __half g_x[(size_t)BATCH * SEQ * FEAT];
__device__ __half g_h1[2][BATCH * HID];
__device__ __half g_h2[2][BATCH * HID];
__device__ float g_c1[BATCH * HID], g_c2[BATCH * HID];
__device__ float g_b1i[NGATE], g_b2i[NGATE];
__device__ unsigned g_bar_count = 0;
__device__ unsigned g_bar_gen = 0;

// ---------------- PTX helpers ----------------
__device__ __forceinline__ uint32_t smem_u32(const void* p) {
    uint32_t a;
    asm("{ .reg .u64 t; cvta.to.shared.u64 t, %1; cvt.u32.u64 %0, t; }" : "=r"(a) : "l"(p));
    return a;
}
__device__ __forceinline__ void cpa(uint32_t dst, const void* src) {
    asm volatile("cp.async.cg.shared.global [%0], [%1], 16;" :: "r"(dst), "l"(src));
}
__device__ __forceinline__ void cp_commit() { asm volatile("cp.async.commit_group;"); }
template <int N> __device__ __forceinline__ void cp_wait() {
    asm volatile("cp.async.wait_group %0;" :: "n"(N));
}
__device__ __forceinline__ void ldm4(uint32_t* r, uint32_t addr) {
    asm volatile("ldmatrix.sync.aligned.m8n8.x4.shared.b16 {%0,%1,%2,%3}, [%4];"
        : "=r"(r[0]), "=r"(r[1]), "=r"(r[2]), "=r"(r[3]) : "r"(addr));
}
__device__ __forceinline__ void mma16816(float* c, const uint32_t* a, const uint32_t* b) {
    asm volatile("mma.sync.aligned.m16n8k16.row.col.f32.f16.f16.f32 "
        "{%0,%1,%2,%3}, {%4,%5,%6,%7}, {%8,%9}, {%0,%1,%2,%3};"
        : "+f"(c[0]), "+f"(c[1]), "+f"(c[2]), "+f"(c[3])
        : "r"(a[0]), "r"(a[1]), "r"(a[2]), "r"(a[3]), "r"(b[0]), "r"(b[1]));
}
__device__ __forceinline__ float sigmoid_(float v) { return 1.0f / (1.0f + __expf(-v)); }

// grid-wide sense-reversing barrier (128 CTAs on distinct SMs: liveness guaranteed)
__device__ __forceinline__ void grid_barrier() {
    __syncthreads();
    if (threadIdx.x == 0) {
        unsigned my = *(volatile unsigned*)&g_bar_gen;
        __threadfence();
        unsigned prev = atomicAdd(&g_bar_count, 1u);
        if (prev == NCTA - 1) {
            atomicExch(&g_bar_count, 0u);
            __threadfence();
            atomicAdd(&g_bar_gen, 1u);
        } else {
            while (*(volatile unsigned*)&g_bar_gen == my) __nanosleep(40);
        }
        __threadfence();
    }
    __syncthreads();
}

// ---------------- one fused LSTM step: both N-tiles, shared A staging, fp16 ----------------
__device__ __forceinline__ void tile_step(
    uint32_t sm_base, int m0, int n0a, int g, int wm, int wn, int lane, int tid,
    const __half* __restrict__ Arec,
    const __half* __restrict__ Urec, int nRec,
    const __half* __restrict__ Ain, int ldaIn,
    const __half* __restrict__ Win, int ldbIn, int nIn,
    const float* __restrict__ biasS, float* __restrict__ cst,
    __half* __restrict__ hout, int first)
{
    __syncthreads();   // previous tile's readers must be done before restaging

    const int n0b = n0a + (NGATE / 2);

    // fixed per-thread staging role: rows sr and sr+64, 16B chunk sc, in each of 3 segs
    const int sr = tid >> 3;            // 0..63
    const int sc = tid & 7;             // 0..7 (16B chunks across 128B row)
    const uint32_t soff = (uint32_t)sr * PB + sc * 16;

    const __half *pA, *pBa, *pBb;
    uint32_t roA, roB;                  // 64-row offsets (elements)

    // per-warp ldmatrix addressing (R12-proven pattern)
    const int rA  = (lane & 7) + ((lane >> 3) & 1) * 8;
    const int kbA = (lane >> 4) * 8;
    const int rB  = (lane & 7) + ((lane >> 4) & 1) * 8;
    const int kbB = ((lane >> 3) & 1) * 8;
    const uint32_t aoff = (uint32_t)(wm * 64 + rA) * PB + kbA * 2;                  // seg0
    const uint32_t boff = (uint32_t)(1 + g) * SEGSZ + (uint32_t)(wn * 32 + rB) * PB + kbB * 2;

    float acc[4][4][4];
    #pragma unroll
    for (int a = 0; a < 4; ++a)
        #pragma unroll
        for (int b = 0; b < 4; ++b)
            #pragma unroll
            for (int c = 0; c < 4; ++c) acc[a][b][c] = 0.0f;

    const int nb = nRec + nIn;

    auto issue = [&](int itL, int s) {
        if (itL == 0 || itL == nRec) {
            if (itL < nRec) {
                pA  = Arec + (size_t)(m0 + sr) * HID + sc * 8;  roA = 64 * HID;
                pBa = Urec + (size_t)(n0a + sr) * HID + sc * 8;
                pBb = Urec + (size_t)(n0b + sr) * HID + sc * 8; roB = 64 * HID;
            } else {
                pA  = Ain + (size_t)(m0 + sr) * ldaIn + sc * 8; roA = 64 * (uint32_t)ldaIn;
                pBa = Win + (size_t)(n0a + sr) * ldbIn + sc * 8;
                pBb = Win + (size_t)(n0b + sr) * ldbIn + sc * 8; roB = 64 * (uint32_t)ldbIn;
            }
        }
        const uint32_t sb = sm_base + (uint32_t)s * STAGE + soff;
        cpa(sb + 0 * SEGSZ,           pA);
        cpa(sb + 0 * SEGSZ + 64 * PB, pA + roA);
        cpa(sb + 1 * SEGSZ,           pBa);
        cpa(sb + 1 * SEGSZ + 64 * PB, pBa + roB);
        cpa(sb + 2 * SEGSZ,           pBb);
        cpa(sb + 2 * SEGSZ + 64 * PB, pBb + roB);
        pA += TK; pBa += TK; pBb += TK;
    };

    // R12-proven 2-stage control flow
    issue(0, 0);
    cp_commit();

    for (int it = 0; it < nb; ++it) {
        if (it + 1 < nb) {
            issue(it + 1, (it + 1) & 1);
            cp_commit();
            cp_wait<1>();
        } else {
            cp_wait<0>();
        }
        __syncthreads();

        const uint32_t sb = sm_base + (uint32_t)(it & 1) * STAGE;
        #pragma unroll
        for (int ks = 0; ks < 4; ++ks) {
            uint32_t bv[2][4];
            #pragma unroll
            for (int p = 0; p < 2; ++p)
                ldm4(bv[p], sb + boff + (uint32_t)p * (16 * PB) + ks * 32);
            uint32_t av[4][4];
            #pragma unroll
            for (int mi = 0; mi < 4; ++mi)
                ldm4(av[mi], sb + aoff + (uint32_t)mi * (16 * PB) + ks * 32);
            #pragma unroll
            for (int mi = 0; mi < 4; ++mi)
                #pragma unroll
                for (int ni = 0; ni < 4; ++ni)
                    mma16816(acc[mi][ni], av[mi], &bv[ni >> 1][(ni & 1) * 2]);
        }
        __syncthreads();
    }

    // epilogue: bias + gate exchange + fused cell
    const int jbase = ((n0a + g * (NGATE / 2)) >> 2) + wn * 8;
    #pragma unroll
    for (int mi = 0; mi < 4; ++mi) {
        #pragma unroll
        for (int ni = 0; ni < 4; ++ni) {
            const int nl = wn * 32 + ni * 8 + (lane & 3) * 2;
            const float bb0 = biasS[nl], bb1 = biasS[nl + 1];
            #pragma unroll
            for (int r = 0; r < 2; ++r) {
                float v0 = acc[mi][ni][r * 2 + 0] + bb0;
                float v1 = acc[mi][ni][r * 2 + 1] + bb1;
                float o0 = __shfl_xor_sync(0xffffffffu, v0, 1);
                float o1 = __shfl_xor_sync(0xffffffffu, v1, 1);
                if ((lane & 1) == 0) {
                    const int m = m0 + wm * 64 + mi * 16 + (lane >> 2) + r * 8;
                    const int j = jbase + ni * 2 + ((lane & 3) >> 1);
                    const size_t idx = (size_t)m * HID + j;
                    float cp = first ? 0.0f : cst[idx];
                    float iv = sigmoid_(v0), fv = sigmoid_(v1);
                    float ci = fmaxf(o0, 0.0f), ov = sigmoid_(o1);
                    float cn = fv * cp + iv * ci;
                    cst[idx] = cn;
                    float hv = ov * fmaxf(cn, 0.0f);
                    hout[idx] = __float2half(hv);
                }
            }
        }
    }
}

// ---------------- persistent kernel: all 128 steps, both layers, dense head ----------------
__global__ __launch_bounds__(NTH, 1) void lstm_persistent(
    const float* __restrict__ Wd, const float* __restrict__ bd, float* __restrict__ out)
{
    extern __shared__ char smem[];
    const uint32_t sm_base = smem_u32(smem);
    float* biasS = reinterpret_cast<float*>(smem + BIAS_OFF);   // [4][128]: L1a,L1b,L2a,L2b

    const int tid  = threadIdx.x;
    const int wid  = tid >> 5;
    const int lane = tid & 31;
    const int g    = wid >> 3;          // warpgroup 0/1 -> N-tile a/b
    const int w8   = wid & 7;
    const int wm   = w8 >> 2;
    const int wn   = w8 & 3;
    const int bid  = blockIdx.x;
    const int m0   = (bid & 15) * TM;
    const int n0a  = (bid >> 4) * TN;

    if (tid < TN) {
        biasS[0 * TN + tid] = g_b1i[n0a + tid];
        biasS[1 * TN + tid] = g_b1i[n0a + (NGATE / 2) + tid];
        biasS[2 * TN + tid] = g_b2i[n0a + tid];
        biasS[3 * TN + tid] = g_b2i[n0a + (NGATE / 2) + tid];
    }
    __syncthreads();

    // phase p: L1(t=p) and L2(t=p-1); both depend only on pre-barrier data
    for (int p = 0; p <= SEQ; ++p) {
        if (p < SEQ) {
            const int t = p, cu = t & 1, pv = (t - 1) & 1;
            tile_step(sm_base, m0, n0a, g, wm, wn, lane, tid,
                      t ? g_h1[pv] : nullptr,
                      g_U1, t ? (HID / TK) : 0,
                      g_x + (size_t)t * FEAT, SEQ * FEAT,
                      g_W1, FEAT, FEAT / TK,
                      biasS + g * TN, g_c1, g_h1[cu], t == 0);
        }
        if (p >= 1) {
            const int t = p - 1, cu = t & 1, pv = (t - 1) & 1;
            tile_step(sm_base, m0, n0a, g, wm, wn, lane, tid,
                      t ? g_h2[pv] : nullptr,
                      g_U2, t ? (HID / TK) : 0,
                      g_h1[cu], HID,
                      g_W2, HID, HID / TK,
                      biasS + (2 + g) * TN, g_c2, g_h2[cu], t == 0);
        }
        grid_barrier();
    }

    // dense head: 128 CTAs x 16 warps = 2048 batch rows
    {
        const int fin = (SEQ - 1) & 1;
        const int b = bid * 16 + wid;
        const __half* rh = g_h2[fin] + (size_t)b * HID;
        float s = 0.0f;
        #pragma unroll
        for (int k = lane; k < HID; k += 32)
            s += __half2float(rh[k]) * Wd[k];
        #pragma unroll
        for (int o = 16; o > 0; o >>= 1) s += __shfl_xor_sync(0xffffffffu, s, o);
        if (lane == 0) out[b] = s + bd[0];
    }
}

// ---------------- prep kernels ----------------
__global__ void prep_weights_all(const float* __restrict__ U1, const float* __restrict__ W1,
                                 const float* __restrict__ U2, const float* __restrict__ W2)
{
    const int NU = NGATE * HID, NW = NGATE * FEAT;
    int idx = blockIdx.x * blockDim.x + threadIdx.x;
    const float* src; __half* d; int K, li;
    if (idx < NU)               { src = U1; d = g_U1; K = HID;  li = idx; }
    else if (idx < NU + NW)     { src = W1; d = g_W1; K = FEAT; li = idx - NU; }
    else if (idx < 2 * NU + NW) { src = U2; d = g_U2; K = HID;  li = idx - NU - NW; }
    else if (idx < 3 * NU + NW) { src = W2; d = g_W2; K = HID;  li = idx - 2 * NU - NW; }
    else return;
    int n = li / K, k = li - n * K;
    int col = (n & 3) * HID + (n >> 2);          // gate-interleave: n = 4j+g
    d[li] = __float2half(src[(size_t)k * NGATE + col]);
}

__global__ void prep_bias(const float* __restrict__ b1, const float* __restrict__ b2)
{
    int n = blockIdx.x * blockDim.x + threadIdx.x;
    if (n >= NGATE) return;
    int col = (n & 3) * HID + (n >> 2);
    g_b1i[n] = b1[col];
    g_b2i[n] = b2[col];
}

__global__ void prep_x(const float* __restrict__ x, int n)
{
    int i = blockIdx.x * blockDim.x + threadIdx.x;
    if (i >= n) return;
    g_x[i] = __float2half(x[i]);
}

extern "C" void kernel_launch(void* const* d_in, const int* in_sizes, int n_in,
                              void* d_out, int out_size)
{
    const float* x  = (const float*)d_in[0];
    const float* W1 = (const float*)d_in[1];
    const float* U1 = (const float*)d_in[2];
    const float* b1 = (const float*)d_in[3];
    const float* W2 = (const float*)d_in[4];
    const float* U2 = (const float*)d_in[5];
    const float* b2 = (const float*)d_in[6];
    const float* Wd = (const float*)d_in[7];
    const float* bd = (const float*)d_in[8];
    float* out = (float*)d_out;

    cudaFuncSetAttribute(lstm_persistent, cudaFuncAttributeMaxDynamicSharedMemorySize, SMEM_DYN);

    {
        int ntot = 3 * NGATE * HID + NGATE * FEAT;
        prep_weights_all<<<(ntot + 255) / 256, 256>>>(U1, W1, U2, W2);
        prep_bias<<<(NGATE + 255) / 256, 256>>>(b1, b2);
        int nx = BATCH * SEQ * FEAT;
        prep_x<<<(nx + 255) / 256, 256>>>(x, nx);
    }

    lstm_persistent<<<NCTA, NTH, SMEM_DYN>>>(Wd, bd, out);
}